// round 4
// baseline (speedup 1.0000x reference)
#include <cuda_runtime.h>
#include <cuda_bf16.h>

// Problem constants (fixed shapes for this problem instance)
#define HH   128
#define WW   128
#define FF   1000
#define KK   8
#define NPIX (HH * WW)            // 16384
#define NSEC (NPIX * KK)          // 131072 elements per (B,H,W,K) section
#define EPSF 1e-8f
#define BIGF 1e10f

// Scratch: packed per-face data (48 KB). 3 float4 per face:
//  [0] = (x0, y0, x1, y1)
//  [1] = (x2, y2, z0, z1)
//  [2] = (z2, z1*z2, z0*z2, z0*z1)
__device__ float4 g_face[FF * 3];

__global__ void precompute_faces(const float* __restrict__ verts,
                                 const int* __restrict__ faces) {
    int f = blockIdx.x * blockDim.x + threadIdx.x;
    if (f >= FF) return;
    int i0 = faces[f * 3 + 0];
    int i1 = faces[f * 3 + 1];
    int i2 = faces[f * 3 + 2];
    float x0 = verts[i0 * 3 + 0], y0 = verts[i0 * 3 + 1], z0 = verts[i0 * 3 + 2];
    float x1 = verts[i1 * 3 + 0], y1 = verts[i1 * 3 + 1], z1 = verts[i1 * 3 + 2];
    float x2 = verts[i2 * 3 + 0], y2 = verts[i2 * 3 + 1], z2 = verts[i2 * 3 + 2];
    g_face[f * 3 + 0] = make_float4(x0, y0, x1, y1);
    g_face[f * 3 + 1] = make_float4(x2, y2, z0, z1);
    g_face[f * 3 + 2] = make_float4(z2, z1 * z2, z0 * z2, z0 * z1);
}

__device__ __forceinline__ float edge_d2(float ax, float ay, float bx, float by,
                                         float px, float py) {
    float ex = bx - ax, ey = by - ay;
    float l2 = fmaxf(ex * ex + ey * ey, EPSF);
    float t = ((px - ax) * ex + (py - ay) * ey) / l2;
    t = fminf(fmaxf(t, 0.0f), 1.0f);
    float dx = px - (ax + t * ex);
    float dy = py - (ay + t * ey);
    return dx * dx + dy * dy;
}

// Block: 128 threads = 16 pixels x 8 face-chunks. Grid: 1024 blocks.
__global__ __launch_bounds__(128) void raster_kernel(float* __restrict__ out) {
    __shared__ float4 sF[FF * 3];   // 48000 bytes

    int tid = threadIdx.x;
    // Stage all face data into shared (reused by 16 pixels)
    for (int i = tid; i < FF * 3; i += 128) sF[i] = g_face[i];
    __syncthreads();

    int p   = tid >> 3;         // pixel slot within block (0..15)
    int sub = tid & 7;          // face-chunk id (0..7)
    int pix = blockIdx.x * 16 + p;
    int x = pix & (WW - 1);
    int y = pix >> 7;
    float px = 1.0f - 2.0f * ((float)x + 0.5f) / (float)WW;
    float py = 1.0f - 2.0f * ((float)y + 0.5f) / (float)HH;

    // Register-resident sorted top-8 (ascending z); stable on ties (strict <).
    float zt[KK];
    int   it[KK];
#pragma unroll
    for (int k = 0; k < KK; k++) { zt[k] = BIGF; it[k] = -1; }

    const int FPC = FF / 8;     // 125 faces per chunk, contiguous index range
    int f0 = sub * FPC;
    for (int f = f0; f < f0 + FPC; ++f) {
        float4 A  = sF[f * 3 + 0];
        float4 Bv = sF[f * 3 + 1];
        float4 C  = sF[f * 3 + 2];
        float x0 = A.x,  y0 = A.y,  x1 = A.z,  y1 = A.w;
        float x2 = Bv.x, y2 = Bv.y, z0 = Bv.z, z1 = Bv.w;
        float z2 = C.x, zz0 = C.y, zz1 = C.z, zz2 = C.w;

        float area = (x1 - x0) * (y2 - y0) - (y1 - y0) * (x2 - x0);
        float w0 = (x2 - x1) * (py - y1) - (y2 - y1) * (px - x1);
        float w1 = (x0 - x2) * (py - y2) - (y0 - y2) * (px - x2);
        float w2 = (x1 - x0) * (py - y0) - (y1 - y0) * (px - x0);

        bool inside;
        if (area > EPSF)        inside = (w0 >= 0.0f) & (w1 >= 0.0f) & (w2 >= 0.0f);
        else if (area < -EPSF)  inside = (w0 <= 0.0f) & (w1 <= 0.0f) & (w2 <= 0.0f);
        else                    inside = false;
        if (!inside) continue;

        // perspective-correct: p_i = m_i / (m0+m1+m2), m_i = w_i * zz_i  (area cancels)
        float m0 = w0 * zz0, m1 = w1 * zz1, m2 = w2 * zz2;
        float inv = 1.0f / (m0 + m1 + m2);
        float zp = (m0 * z0 + m1 * z1 + m2 * z2) * inv;

        if (zp < zt[KK - 1]) {
            zt[KK - 1] = zp; it[KK - 1] = f;
#pragma unroll
            for (int k = KK - 1; k > 0; --k) {
                if (zt[k] < zt[k - 1]) {
                    float tz = zt[k]; zt[k] = zt[k - 1]; zt[k - 1] = tz;
                    int   ti = it[k]; it[k] = it[k - 1]; it[k - 1] = ti;
                }
            }
        }
    }

    // Merge 8 chunk-lists per pixel via warp shuffles into sub==0's list.
    // Chunks processed in ascending face-index order + strict-< insertion
    // => matches top_k's stable tie ordering.
    const unsigned FULLM = 0xffffffffu;
    int lane = tid & 31;
    int base = lane & ~7;
    for (int s = 1; s < 8; ++s) {
#pragma unroll
        for (int k = 0; k < KK; k++) {
            float z = __shfl_sync(FULLM, zt[k], base + s);
            int   i = __shfl_sync(FULLM, it[k], base + s);
            if (sub == 0) {
                if (z < zt[KK - 1]) {
                    zt[KK - 1] = z; it[KK - 1] = i;
#pragma unroll
                    for (int m = KK - 1; m > 0; --m) {
                        if (zt[m] < zt[m - 1]) {
                            float tz = zt[m]; zt[m] = zt[m - 1]; zt[m - 1] = tz;
                            int   ti = it[m]; it[m] = it[m - 1]; it[m - 1] = ti;
                        }
                    }
                }
            }
        }
    }

    // Redistribute: thread `sub` handles output slot k = sub of its pixel.
    float myz = BIGF; int myf = -1;
#pragma unroll
    for (int k = 0; k < KK; k++) {
        float z = __shfl_sync(FULLM, zt[k], base);
        int   i = __shfl_sync(FULLM, it[k], base);
        if (sub == k) { myz = z; myf = i; }
    }

    int o = pix * KK + sub;
    float* o_p2f  = out;                // (H,W,K)
    float* o_zbuf = out + NSEC;         // (H,W,K)
    float* o_bary = out + 2 * NSEC;     // (H,W,K,3)
    float* o_dist = out + 5 * NSEC;     // (H,W,K)

    if (myz < 0.5f * BIGF) {
        int f = myf;
        float4 A  = sF[f * 3 + 0];
        float4 Bv = sF[f * 3 + 1];
        float4 C  = sF[f * 3 + 2];
        float x0 = A.x,  y0 = A.y,  x1 = A.z,  y1 = A.w;
        float x2 = Bv.x, y2 = Bv.y, z0 = Bv.z, z1 = Bv.w;
        float zz0 = C.y, zz1 = C.z, zz2 = C.w;

        float w0 = (x2 - x1) * (py - y1) - (y2 - y1) * (px - x1);
        float w1 = (x0 - x2) * (py - y2) - (y0 - y2) * (px - x2);
        float w2 = (x1 - x0) * (py - y0) - (y1 - y0) * (px - x0);
        float m0 = w0 * zz0, m1 = w1 * zz1, m2 = w2 * zz2;
        float inv = 1.0f / (m0 + m1 + m2);
        float p0 = m0 * inv, p1 = m1 * inv, p2 = m2 * inv;

        float d2 = fminf(edge_d2(x0, y0, x1, y1, px, py),
                   fminf(edge_d2(x1, y1, x2, y2, px, py),
                         edge_d2(x2, y2, x0, y0, px, py)));

        o_p2f[o]  = (float)f;
        o_zbuf[o] = myz;
        o_bary[o * 3 + 0] = p0;
        o_bary[o * 3 + 1] = p1;
        o_bary[o * 3 + 2] = p2;
        o_dist[o] = -d2;   // valid => inside => sd = -d2
    } else {
        o_p2f[o]  = -1.0f;
        o_zbuf[o] = -1.0f;
        o_bary[o * 3 + 0] = -1.0f;
        o_bary[o * 3 + 1] = -1.0f;
        o_bary[o * 3 + 2] = -1.0f;
        o_dist[o] = -1.0f;
    }
}

extern "C" void kernel_launch(void* const* d_in, const int* in_sizes, int n_in,
                              void* d_out, int out_size) {
    // vertices: 1*600*3 = 1800 floats; faces: 1*1000*3 = 3000 ints.
    const float* verts;
    const int* faces;
    if (in_sizes[0] == 1800) {
        verts = (const float*)d_in[0];
        faces = (const int*)d_in[1];
    } else {
        verts = (const float*)d_in[1];
        faces = (const int*)d_in[0];
    }
    float* out = (float*)d_out;

    precompute_faces<<<4, 256>>>(verts, faces);
    raster_kernel<<<NPIX / 16, 128>>>(out);
}

// round 5
// speedup vs baseline: 1.5991x; 1.5991x over previous
#include <cuda_runtime.h>
#include <cuda_bf16.h>
#include <math_constants.h>

// Problem constants (fixed shapes for this problem instance)
#define HH   128
#define WW   128
#define FF   1000
#define KK   8
#define NPIX (HH * WW)            // 16384
#define NSEC (NPIX * KK)          // 131072 elements per (B,H,W,K) section
#define EPSF 1e-8f
#define BIGF 1e10f

// Scratch: packed per-face data (48 KB). 3 float4 per face:
//  [0] = (x0, y0, x1, y1)
//  [1] = (x2, y2, z0, z1)
//  [2] = (z2, s*z1*z2, s*z0*z2, s*z0*z1)   s = sign(area), NaN if |area|<=EPS
__device__ float4 g_face[FF * 3];

__global__ void precompute_faces(const float* __restrict__ verts,
                                 const int* __restrict__ faces) {
    int f = blockIdx.x * blockDim.x + threadIdx.x;
    if (f >= FF) return;
    int i0 = faces[f * 3 + 0];
    int i1 = faces[f * 3 + 1];
    int i2 = faces[f * 3 + 2];
    float x0 = verts[i0 * 3 + 0], y0 = verts[i0 * 3 + 1], z0 = verts[i0 * 3 + 2];
    float x1 = verts[i1 * 3 + 0], y1 = verts[i1 * 3 + 1], z1 = verts[i1 * 3 + 2];
    float x2 = verts[i2 * 3 + 0], y2 = verts[i2 * 3 + 1], z2 = verts[i2 * 3 + 2];
    float area = (x1 - x0) * (y2 - y0) - (y1 - y0) * (x2 - x0);
    float s;
    if (area > EPSF)       s = 1.0f;
    else if (area < -EPSF) s = -1.0f;
    else                   s = CUDART_NAN_F;   // NaN => inside-test always fails
    g_face[f * 3 + 0] = make_float4(x0, y0, x1, y1);
    g_face[f * 3 + 1] = make_float4(x2, y2, z0, z1);
    g_face[f * 3 + 2] = make_float4(z2, s * z1 * z2, s * z0 * z2, s * z0 * z1);
}

__device__ __forceinline__ float edge_d2(float ax, float ay, float bx, float by,
                                         float px, float py) {
    float ex = bx - ax, ey = by - ay;
    float l2 = fmaxf(ex * ex + ey * ey, EPSF);
    float t = ((px - ax) * ex + (py - ay) * ey) / l2;
    t = fminf(fmaxf(t, 0.0f), 1.0f);
    float dx = px - (ax + t * ex);
    float dy = py - (ay + t * ey);
    return dx * dx + dy * dy;
}

// Block: 256 threads = 32 pixels x 8 face-chunks. Grid: 512 blocks (single wave).
__global__ __launch_bounds__(256) void raster_kernel(float* __restrict__ out) {
    __shared__ float4 sF[FF * 3];   // 48000 bytes

    int tid = threadIdx.x;
    // Stage all face data into shared (reused by 32 pixels)
    for (int i = tid; i < FF * 3; i += 256) sF[i] = g_face[i];
    __syncthreads();

    int p   = tid >> 3;         // pixel slot within block (0..31)
    int sub = tid & 7;          // face-chunk id (0..7)
    int pix = blockIdx.x * 32 + p;
    int x = pix & (WW - 1);
    int y = pix >> 7;
    float px = 1.0f - 2.0f * ((float)x + 0.5f) / (float)WW;
    float py = 1.0f - 2.0f * ((float)y + 0.5f) / (float)HH;

    // Register-resident sorted top-8 (ascending z); stable on ties (strict <).
    float zt[KK];
    int   it[KK];
#pragma unroll
    for (int k = 0; k < KK; k++) { zt[k] = BIGF; it[k] = -1; }

    const int FPC = FF / 8;     // 125 faces per chunk, contiguous index range
    int f0 = sub * FPC;
    for (int f = f0; f < f0 + FPC; ++f) {
        float4 A  = sF[f * 3 + 0];
        float4 Bv = sF[f * 3 + 1];
        float4 C  = sF[f * 3 + 2];
        float x0 = A.x,  y0 = A.y,  x1 = A.z,  y1 = A.w;
        float x2 = Bv.x, y2 = Bv.y, z0 = Bv.z, z1 = Bv.w;
        float z2 = C.x, szz0 = C.y, szz1 = C.z, szz2 = C.w;

        // same textual form as reference (rounding-compatible)
        float w0 = (x2 - x1) * (py - y1) - (y2 - y1) * (px - x1);
        float w1 = (x0 - x2) * (py - y2) - (y0 - y2) * (px - x2);
        float w2 = (x1 - x0) * (py - y0) - (y1 - y0) * (px - x0);

        // m_i = s * w_i * zz_i ; zz_i > 0 so sign(m_i) = s*sign(w_i).
        // inside <=> all m_i >= 0 (NaN szz for degenerate faces fails all tests)
        float m0 = w0 * szz0, m1 = w1 * szz1, m2 = w2 * szz2;
        if ((m0 >= 0.0f) & (m1 >= 0.0f) & (m2 >= 0.0f)) {
            float den = m0 + m1 + m2;                      // > 0 when inside
            float num = m0 * z0 + m1 * z1 + m2 * z2;
            if (num < zt[KK - 1] * den) {                  // deferred division
                float zp = num / den;
                zt[KK - 1] = zp; it[KK - 1] = f;
#pragma unroll
                for (int k = KK - 1; k > 0; --k) {
                    if (zt[k] < zt[k - 1]) {
                        float tz = zt[k]; zt[k] = zt[k - 1]; zt[k - 1] = tz;
                        int   ti = it[k]; it[k] = it[k - 1]; it[k - 1] = ti;
                    }
                }
            }
        }
    }

    // Merge 8 chunk-lists per pixel via warp shuffles into sub==0's list.
    // Chunks processed in ascending face-index order + strict-< insertion
    // => matches top_k's stable tie ordering.
    const unsigned FULLM = 0xffffffffu;
    int lane = tid & 31;
    int base = lane & ~7;
    for (int s = 1; s < 8; ++s) {
#pragma unroll
        for (int k = 0; k < KK; k++) {
            float z = __shfl_sync(FULLM, zt[k], base + s);
            int   i = __shfl_sync(FULLM, it[k], base + s);
            if (sub == 0) {
                if (z < zt[KK - 1]) {
                    zt[KK - 1] = z; it[KK - 1] = i;
#pragma unroll
                    for (int m = KK - 1; m > 0; --m) {
                        if (zt[m] < zt[m - 1]) {
                            float tz = zt[m]; zt[m] = zt[m - 1]; zt[m - 1] = tz;
                            int   ti = it[m]; it[m] = it[m - 1]; it[m - 1] = ti;
                        }
                    }
                }
            }
        }
    }

    // Redistribute: thread `sub` handles output slot k = sub of its pixel.
    float myz = BIGF; int myf = -1;
#pragma unroll
    for (int k = 0; k < KK; k++) {
        float z = __shfl_sync(FULLM, zt[k], base);
        int   i = __shfl_sync(FULLM, it[k], base);
        if (sub == k) { myz = z; myf = i; }
    }

    int o = pix * KK + sub;
    float* o_p2f  = out;                // (H,W,K)
    float* o_zbuf = out + NSEC;         // (H,W,K)
    float* o_bary = out + 2 * NSEC;     // (H,W,K,3)
    float* o_dist = out + 5 * NSEC;     // (H,W,K)

    if (myz < 0.5f * BIGF) {
        int f = myf;
        float4 A  = sF[f * 3 + 0];
        float4 Bv = sF[f * 3 + 1];
        float4 C  = sF[f * 3 + 2];
        float x0 = A.x,  y0 = A.y,  x1 = A.z,  y1 = A.w;
        float x2 = Bv.x, y2 = Bv.y;
        float szz0 = C.y, szz1 = C.z, szz2 = C.w;

        float w0 = (x2 - x1) * (py - y1) - (y2 - y1) * (px - x1);
        float w1 = (x0 - x2) * (py - y2) - (y0 - y2) * (px - x2);
        float w2 = (x1 - x0) * (py - y0) - (y1 - y0) * (px - x0);
        float m0 = w0 * szz0, m1 = w1 * szz1, m2 = w2 * szz2;   // s cancels in ratios
        float inv = 1.0f / (m0 + m1 + m2);
        float p0 = m0 * inv, p1 = m1 * inv, p2 = m2 * inv;

        float d2 = fminf(edge_d2(x0, y0, x1, y1, px, py),
                   fminf(edge_d2(x1, y1, x2, y2, px, py),
                         edge_d2(x2, y2, x0, y0, px, py)));

        o_p2f[o]  = (float)f;
        o_zbuf[o] = myz;
        o_bary[o * 3 + 0] = p0;
        o_bary[o * 3 + 1] = p1;
        o_bary[o * 3 + 2] = p2;
        o_dist[o] = -d2;   // valid => inside => sd = -d2
    } else {
        o_p2f[o]  = -1.0f;
        o_zbuf[o] = -1.0f;
        o_bary[o * 3 + 0] = -1.0f;
        o_bary[o * 3 + 1] = -1.0f;
        o_bary[o * 3 + 2] = -1.0f;
        o_dist[o] = -1.0f;
    }
}

extern "C" void kernel_launch(void* const* d_in, const int* in_sizes, int n_in,
                              void* d_out, int out_size) {
    // vertices: 1*600*3 = 1800 floats; faces: 1*1000*3 = 3000 ints.
    const float* verts;
    const int* faces;
    if (in_sizes[0] == 1800) {
        verts = (const float*)d_in[0];
        faces = (const int*)d_in[1];
    } else {
        verts = (const float*)d_in[1];
        faces = (const int*)d_in[0];
    }
    float* out = (float*)d_out;

    precompute_faces<<<4, 256>>>(verts, faces);
    raster_kernel<<<NPIX / 32, 256>>>(out);
}

// round 7
// speedup vs baseline: 1.7932x; 1.1214x over previous
#include <cuda_runtime.h>
#include <cuda_bf16.h>
#include <math_constants.h>

// Problem constants (fixed shapes for this problem instance)
#define HH   128
#define WW   128
#define FF   1000
#define KK   8
#define NPIX (HH * WW)            // 16384
#define NSEC (NPIX * KK)          // 131072 elements per (B,H,W,K) section
#define EPSF 1e-8f
#define BIGF 1e10f

#define TILES_X 8                 // 8x8 tiles of 16x16 pixels
#define NTILES  64
#define TPAD    1e-5f             // conservative tile-bound padding

// Scratch: packed per-face data (48 KB). 3 float4 per face:
//  [0] = (x0, y0, x1, y1)
//  [1] = (x2, y2, z0, z1)
//  [2] = (z2, s*z1*z2, s*z0*z2, s*z0*z1)   s = sign(area), NaN if |area|<=EPS
__device__ float4 g_face[FF * 3];
__device__ float4 g_bbox[FF];          // (xmin, xmax, ymin, ymax) in NDC
__device__ int    g_list[NTILES * FF]; // per-tile face lists (ascending order)
__device__ int    g_cnt[NTILES];

__global__ void precompute_faces(const float* __restrict__ verts,
                                 const int* __restrict__ faces) {
    int f = blockIdx.x * blockDim.x + threadIdx.x;
    if (f >= FF) return;
    int i0 = faces[f * 3 + 0];
    int i1 = faces[f * 3 + 1];
    int i2 = faces[f * 3 + 2];
    float x0 = verts[i0 * 3 + 0], y0 = verts[i0 * 3 + 1], z0 = verts[i0 * 3 + 2];
    float x1 = verts[i1 * 3 + 0], y1 = verts[i1 * 3 + 1], z1 = verts[i1 * 3 + 2];
    float x2 = verts[i2 * 3 + 0], y2 = verts[i2 * 3 + 1], z2 = verts[i2 * 3 + 2];
    float area = (x1 - x0) * (y2 - y0) - (y1 - y0) * (x2 - x0);
    float s;
    if (area > EPSF)       s = 1.0f;
    else if (area < -EPSF) s = -1.0f;
    else                   s = CUDART_NAN_F;   // NaN => inside-test always fails
    g_face[f * 3 + 0] = make_float4(x0, y0, x1, y1);
    g_face[f * 3 + 1] = make_float4(x2, y2, z0, z1);
    g_face[f * 3 + 2] = make_float4(z2, s * z1 * z2, s * z0 * z2, s * z0 * z1);
    g_bbox[f] = make_float4(fminf(x0, fminf(x1, x2)), fmaxf(x0, fmaxf(x1, x2)),
                            fminf(y0, fminf(y1, y2)), fmaxf(y0, fmaxf(y1, y2)));
}

// One warp per tile: ballot-compacted, order-preserving bbox binning.
__global__ __launch_bounds__(32) void bin_faces() {
    int tile = blockIdx.x;
    int lane = threadIdx.x;
    int tx = tile & (TILES_X - 1);
    int ty = tile / TILES_X;
    // px decreases with x, py decreases with y
    float px_hi = 1.0f - 2.0f * ((float)(16 * tx) + 0.5f) / (float)WW + TPAD;
    float px_lo = 1.0f - 2.0f * ((float)(16 * tx + 15) + 0.5f) / (float)WW - TPAD;
    float py_hi = 1.0f - 2.0f * ((float)(16 * ty) + 0.5f) / (float)HH + TPAD;
    float py_lo = 1.0f - 2.0f * ((float)(16 * ty + 15) + 0.5f) / (float)HH - TPAD;

    int count = 0;
    for (int base = 0; base < FF; base += 32) {
        int f = base + lane;
        bool ov = false;
        if (f < FF) {
            float4 bb = g_bbox[f];
            ov = (bb.x <= px_hi) & (bb.y >= px_lo) & (bb.z <= py_hi) & (bb.w >= py_lo);
        }
        unsigned m = __ballot_sync(0xffffffffu, ov);
        if (ov)
            g_list[tile * FF + count + __popc(m & ((1u << lane) - 1u))] = f;
        count += __popc(m);
    }
    if (lane == 0) g_cnt[tile] = count;
}

__device__ __forceinline__ float edge_d2(float ax, float ay, float bx, float by,
                                         float px, float py) {
    float ex = bx - ax, ey = by - ay;
    float l2 = fmaxf(ex * ex + ey * ey, EPSF);
    float t = ((px - ax) * ex + (py - ay) * ey) / l2;
    t = fminf(fmaxf(t, 0.0f), 1.0f);
    float dx = px - (ax + t * ex);
    float dy = py - (ay + t * ey);
    return dx * dx + dy * dy;
}

// Grid: 512 blocks = 64 tiles x 8 sub-blocks. Block: 256 threads = 32 pixels x 8 chunks.
// Each block stages its tile's face list into dynamic shared (52000 B).
__global__ __launch_bounds__(256) void raster_kernel(float* __restrict__ out) {
    extern __shared__ char smem[];
    float4* sFd   = (float4*)smem;              // 1000*48 = 48000 B
    int*    s_idx = (int*)(smem + FF * 48);     // 1000*4  =  4000 B

    int tid  = threadIdx.x;
    int tile = blockIdx.x >> 3;
    int sb   = blockIdx.x & 7;
    int len  = g_cnt[tile];

    // Stage this tile's face data + indices into shared
    for (int i = tid; i < len; i += 256) {
        int f = g_list[tile * FF + i];
        s_idx[i] = f;
        sFd[i * 3 + 0] = g_face[f * 3 + 0];
        sFd[i * 3 + 1] = g_face[f * 3 + 1];
        sFd[i * 3 + 2] = g_face[f * 3 + 2];
    }
    __syncthreads();

    int p   = tid >> 3;         // pixel slot within block (0..31)
    int sub = tid & 7;          // face-chunk id (0..7)
    int tx  = tile & (TILES_X - 1);
    int ty  = tile / TILES_X;
    int x   = 16 * tx + (p & 15);
    int y   = 16 * ty + sb * 2 + (p >> 4);   // sub-block owns 2 rows of the tile
    int pix = y * WW + x;
    float px = 1.0f - 2.0f * ((float)x + 0.5f) / (float)WW;
    float py = 1.0f - 2.0f * ((float)y + 0.5f) / (float)HH;

    // Register-resident sorted top-8 (ascending z). Carries list POSITION.
    float zt[KK];
    int   it[KK];
#pragma unroll
    for (int k = 0; k < KK; k++) { zt[k] = BIGF; it[k] = -1; }

    // Strided over list positions: 8 subs read 8 consecutive faces -> conflict-free LDS
    for (int pos = sub; pos < len; pos += 8) {
        float4 A  = sFd[pos * 3 + 0];
        float4 Bv = sFd[pos * 3 + 1];
        float4 C  = sFd[pos * 3 + 2];
        float x0 = A.x,  y0 = A.y,  x1 = A.z,  y1 = A.w;
        float x2 = Bv.x, y2 = Bv.y, z0 = Bv.z, z1 = Bv.w;
        float z2 = C.x, szz0 = C.y, szz1 = C.z, szz2 = C.w;

        // same textual form as reference (rounding-compatible)
        float w0 = (x2 - x1) * (py - y1) - (y2 - y1) * (px - x1);
        float w1 = (x0 - x2) * (py - y2) - (y0 - y2) * (px - x2);
        float w2 = (x1 - x0) * (py - y0) - (y1 - y0) * (px - x0);

        // m_i = s * w_i * zz_i ; zz_i > 0 so sign(m_i) = s*sign(w_i).
        float m0 = w0 * szz0, m1 = w1 * szz1, m2 = w2 * szz2;
        if ((m0 >= 0.0f) & (m1 >= 0.0f) & (m2 >= 0.0f)) {
            float den = m0 + m1 + m2;                      // > 0 when inside
            float num = m0 * z0 + m1 * z1 + m2 * z2;
            if (num < zt[KK - 1] * den) {                  // deferred division
                float zp = num / den;
                zt[KK - 1] = zp; it[KK - 1] = pos;
#pragma unroll
                for (int k = KK - 1; k > 0; --k) {
                    if (zt[k] < zt[k - 1]) {
                        float tz = zt[k]; zt[k] = zt[k - 1]; zt[k - 1] = tz;
                        int   ti = it[k]; it[k] = it[k - 1]; it[k - 1] = ti;
                    }
                }
            }
        }
    }

    // Merge 8 chunk-lists per pixel via warp shuffles into sub==0's list.
    const unsigned FULLM = 0xffffffffu;
    int lane = tid & 31;
    int base = lane & ~7;
    for (int s = 1; s < 8; ++s) {
#pragma unroll
        for (int k = 0; k < KK; k++) {
            float z = __shfl_sync(FULLM, zt[k], base + s);
            int   i = __shfl_sync(FULLM, it[k], base + s);
            if (sub == 0) {
                if (z < zt[KK - 1]) {
                    zt[KK - 1] = z; it[KK - 1] = i;
#pragma unroll
                    for (int m = KK - 1; m > 0; --m) {
                        if (zt[m] < zt[m - 1]) {
                            float tz = zt[m]; zt[m] = zt[m - 1]; zt[m - 1] = tz;
                            int   ti = it[m]; it[m] = it[m - 1]; it[m - 1] = ti;
                        }
                    }
                }
            }
        }
    }

    // Redistribute: thread `sub` handles output slot k = sub of its pixel.
    float myz = BIGF; int mypos = -1;
#pragma unroll
    for (int k = 0; k < KK; k++) {
        float z = __shfl_sync(FULLM, zt[k], base);
        int   i = __shfl_sync(FULLM, it[k], base);
        if (sub == k) { myz = z; mypos = i; }
    }

    int o = pix * KK + sub;
    float* o_p2f  = out;                // (H,W,K)
    float* o_zbuf = out + NSEC;         // (H,W,K)
    float* o_bary = out + 2 * NSEC;     // (H,W,K,3)
    float* o_dist = out + 5 * NSEC;     // (H,W,K)

    if (myz < 0.5f * BIGF) {
        float4 A  = sFd[mypos * 3 + 0];
        float4 Bv = sFd[mypos * 3 + 1];
        float4 C  = sFd[mypos * 3 + 2];
        int f = s_idx[mypos];
        float x0 = A.x,  y0 = A.y,  x1 = A.z,  y1 = A.w;
        float x2 = Bv.x, y2 = Bv.y;
        float szz0 = C.y, szz1 = C.z, szz2 = C.w;

        float w0 = (x2 - x1) * (py - y1) - (y2 - y1) * (px - x1);
        float w1 = (x0 - x2) * (py - y2) - (y0 - y2) * (px - x2);
        float w2 = (x1 - x0) * (py - y0) - (y1 - y0) * (px - x0);
        float m0 = w0 * szz0, m1 = w1 * szz1, m2 = w2 * szz2;   // s cancels in ratios
        float inv = 1.0f / (m0 + m1 + m2);
        float p0 = m0 * inv, p1 = m1 * inv, p2 = m2 * inv;

        float d2 = fminf(edge_d2(x0, y0, x1, y1, px, py),
                   fminf(edge_d2(x1, y1, x2, y2, px, py),
                         edge_d2(x2, y2, x0, y0, px, py)));

        o_p2f[o]  = (float)f;
        o_zbuf[o] = myz;
        o_bary[o * 3 + 0] = p0;
        o_bary[o * 3 + 1] = p1;
        o_bary[o * 3 + 2] = p2;
        o_dist[o] = -d2;   // valid => inside => sd = -d2
    } else {
        o_p2f[o]  = -1.0f;
        o_zbuf[o] = -1.0f;
        o_bary[o * 3 + 0] = -1.0f;
        o_bary[o * 3 + 1] = -1.0f;
        o_bary[o * 3 + 2] = -1.0f;
        o_dist[o] = -1.0f;
    }
}

extern "C" void kernel_launch(void* const* d_in, const int* in_sizes, int n_in,
                              void* d_out, int out_size) {
    // vertices: 1*600*3 = 1800 floats; faces: 1*1000*3 = 3000 ints.
    const float* verts;
    const int* faces;
    if (in_sizes[0] == 1800) {
        verts = (const float*)d_in[0];
        faces = (const int*)d_in[1];
    } else {
        verts = (const float*)d_in[1];
        faces = (const int*)d_in[0];
    }
    float* out = (float*)d_out;

    const int SMEM_BYTES = FF * 48 + FF * 4;   // 52000
    cudaFuncSetAttribute(raster_kernel,
                         cudaFuncAttributeMaxDynamicSharedMemorySize, SMEM_BYTES);

    precompute_faces<<<4, 256>>>(verts, faces);
    bin_faces<<<NTILES, 32>>>();
    raster_kernel<<<NTILES * 8, 256, SMEM_BYTES>>>(out);
}